// round 1
// baseline (speedup 1.0000x reference)
#include <cuda_runtime.h>
#include <math.h>

#define N 768
#define NT 50
#define NN (N*N)
#define SIGMA 0.1f
#define RES 100
#define NL 5
#define S_ITERS 14   // max squaring iterations: s <= 14 -> q = s-1 <= 13

// Taylor coefficients 1/k!
#define C0  1.0f
#define C1  1.0f
#define C2  0.5f
#define C3  (1.0f/6.0f)
#define C4  (1.0f/24.0f)
#define C5  (1.0f/120.0f)
#define C6  (1.0f/720.0f)
#define C7  (1.0f/5040.0f)
#define C8  (1.0f/40320.0f)
#define C9  (1.0f/362880.0f)
#define C10 (1.0f/3628800.0f)
#define C11 (1.0f/39916800.0f)
#define C12 (2.0876757e-9f)
#define C13 (1.6059044e-10f)
#define C14 (1.1470746e-11f)
#define C15 (7.6471637e-13f)

// Scratch (static device arrays; ~710 MB total)
__device__ float g_dist[NN];
__device__ float g_r[NT*N];
__device__ float g_rmax[NT];
__device__ int   g_s[NT];
__device__ int   g_q[NT];
__device__ float g_scale[NT];
__device__ float g_maxdist;
__device__ float g_betti[NT];
// buffers: 0=M 1=M2 2=M3 3=M4 4/5 = ping-pong (Taylor result lands in 5)
__device__ float g_buf[6][(size_t)NT*NN];

__device__ __forceinline__ void atomicMaxF(float* addr, float v) {
    // valid for non-negative floats
    atomicMax((int*)addr, __float_as_int(v));
}

__global__ void init_kernel() {
    int t = threadIdx.x;
    if (t < NT) g_rmax[t] = 0.0f;
    if (t == 0) g_maxdist = 0.0f;
}

__global__ void dist_kernel(const float* __restrict__ pts) {
    __shared__ float p[N*3];
    for (int i = threadIdx.x; i < N*3; i += blockDim.x) p[i] = pts[i];
    __syncthreads();
    int idx = blockIdx.x * blockDim.x + threadIdx.x;
    float d = 0.0f;
    if (idx < NN) {
        int i = idx / N, j = idx - i*N;
        float dx = p[i*3+0] - p[j*3+0];
        float dy = p[i*3+1] - p[j*3+1];
        float dz = p[i*3+2] - p[j*3+2];
        d = sqrtf(dx*dx + dy*dy + dz*dz);
        g_dist[idx] = d;
    }
    __shared__ float red[256];
    red[threadIdx.x] = d;
    __syncthreads();
    for (int off = 128; off > 0; off >>= 1) {
        if (threadIdx.x < off) red[threadIdx.x] = fmaxf(red[threadIdx.x], red[threadIdx.x+off]);
        __syncthreads();
    }
    if (threadIdx.x == 0) atomicMaxF(&g_maxdist, red[0]);
}

// one block per (t, i): off-diagonal row sums of soft adjacency
__global__ void rowsum_kernel() {
    int bid = blockIdx.x;           // t*N + i
    int t = bid / N, i = bid - t*N;
    float th = ((float)t / (float)(NT-1)) * g_maxdist;
    const float* drow = g_dist + (size_t)i*N;
    float s = 0.0f;
    for (int j = threadIdx.x; j < N; j += blockDim.x) {
        if (j != i) {
            float e = expf((drow[j] - th) / SIGMA);   // inf -> term 0, fine
            s += 1.0f / (1.0f + e);
        }
    }
    __shared__ float red[128];
    red[threadIdx.x] = s;
    __syncthreads();
    for (int off = 64; off > 0; off >>= 1) {
        if (threadIdx.x < off) red[threadIdx.x] += red[threadIdx.x+off];
        __syncthreads();
    }
    if (threadIdx.x == 0) {
        g_r[bid] = red[0];
        atomicMaxF(&g_rmax[t], red[0]);
    }
}

__global__ void sq_kernel() {
    int t = threadIdx.x;
    if (t < NT) {
        float x = 2.0f * g_rmax[t] / SIGMA;   // ||L||_inf / sigma bound
        int s = 0;
        if (x > 1.0f) s = (int)ceilf(log2f(x));
        if (s < 0) s = 0;
        if (s > 15) s = 15;
        g_s[t] = s;
        g_q[t] = (s > 1) ? (s - 1) : 0;
        g_scale[t] = exp2f((float)(-s)) / SIGMA;
    }
}

// M = -L/(sigma*2^s): off-diag = +A_ij*scale, diag = -r_i*scale
__global__ void buildM_kernel() {
    int t = blockIdx.y;
    int idx = blockIdx.x * blockDim.x + threadIdx.x;
    if (idx >= NN) return;
    int i = idx / N, j = idx - i*N;
    float th = ((float)t / (float)(NT-1)) * g_maxdist;
    float sc = g_scale[t];
    float v;
    if (i == j) {
        v = -g_r[t*N + i] * sc;
    } else {
        float e = expf((g_dist[idx] - th) / SIGMA);
        v = sc / (1.0f + e);
    }
    g_buf[0][(size_t)t*NN + idx] = v;
}

// buf4 = C12*I + C13*M + C14*M2 + C15*M3
__global__ void elw_g3_kernel() {
    int t = blockIdx.y;
    int idx = blockIdx.x * blockDim.x + threadIdx.x;
    if (idx >= NN) return;
    int i = idx / N, j = idx - i*N;
    size_t o = (size_t)t*NN + idx;
    float v = C13*g_buf[0][o] + C14*g_buf[1][o] + C15*g_buf[2][o];
    if (i == j) v += C12;
    g_buf[4][o] = v;
}

// Batched symmetric-output GEMM: C = A*B (+ optional gc0*I+gc1*M+gc2*M2+gc3*M3)
// Only lower-triangle 128x128 tiles computed; mirrored to upper (result is
// symmetric: all operands are polynomials in the same symmetric M).
__global__ void __launch_bounds__(256) gemm_kernel(int ai, int bi, int ci, int addG,
                                                   float gc0, float gc1, float gc2, float gc3,
                                                   int iter)
{
    int t = blockIdx.z;
    if (iter >= 0 && iter >= g_q[t]) return;

    // decode lower-triangular tile index (21 tiles for 6x6)
    int r = 0, rem = blockIdx.x;
    while (rem > r) { rem -= (r + 1); r++; }
    int btr = r, btc = rem;            // tile row >= tile col

    const float* A = g_buf[ai] + (size_t)t*NN;
    const float* B = g_buf[bi] + (size_t)t*NN;
    float*       C = g_buf[ci] + (size_t)t*NN;

    __shared__ float As[16][132];
    __shared__ float Bs[16][128];

    int tid = threadIdx.x;
    int tx = tid & 15, ty = tid >> 4;
    int row0 = btr * 128, col0 = btc * 128;

    float acc[8][8];
    #pragma unroll
    for (int i = 0; i < 8; i++)
        #pragma unroll
        for (int j = 0; j < 8; j++) acc[i][j] = 0.0f;

    for (int kk = 0; kk < N; kk += 16) {
        // A tile 128x16, transposed into As[k][m]
        #pragma unroll
        for (int l = 0; l < 2; l++) {
            int id = tid*2 + l;                 // 0..511
            int m = id >> 2, g4 = id & 3;
            float4 v = *(const float4*)&A[(size_t)(row0 + m)*N + kk + g4*4];
            As[g4*4+0][m] = v.x; As[g4*4+1][m] = v.y;
            As[g4*4+2][m] = v.z; As[g4*4+3][m] = v.w;
        }
        // B tile 16x128
        #pragma unroll
        for (int l = 0; l < 2; l++) {
            int id = tid*2 + l;
            int kb = id >> 5, f = id & 31;
            *(float4*)&Bs[kb][f*4] = *(const float4*)&B[(size_t)(kk + kb)*N + col0 + f*4];
        }
        __syncthreads();
        #pragma unroll
        for (int k = 0; k < 16; k++) {
            float a[8], b[8];
            *(float4*)(a)   = *(float4*)&As[k][ty*8];
            *(float4*)(a+4) = *(float4*)&As[k][ty*8+4];
            *(float4*)(b)   = *(float4*)&Bs[k][tx*8];
            *(float4*)(b+4) = *(float4*)&Bs[k][tx*8+4];
            #pragma unroll
            for (int i = 0; i < 8; i++)
                #pragma unroll
                for (int j = 0; j < 8; j++)
                    acc[i][j] += a[i] * b[j];
        }
        __syncthreads();
    }

    if (addG) {
        const float* M  = g_buf[0] + (size_t)t*NN;
        const float* M2 = g_buf[1] + (size_t)t*NN;
        const float* M3 = g_buf[2] + (size_t)t*NN;
        #pragma unroll
        for (int i = 0; i < 8; i++) {
            int rr = row0 + ty*8 + i;
            #pragma unroll
            for (int j = 0; j < 8; j++) {
                int cc = col0 + tx*8 + j;
                size_t o = (size_t)rr*N + cc;
                float g = gc1*M[o] + gc2*M2[o] + gc3*M3[o];
                if (rr == cc) g += gc0;
                acc[i][j] += g;
            }
        }
    }

    // store lower tile (coalesced)
    #pragma unroll
    for (int i = 0; i < 8; i++) {
        int rr = row0 + ty*8 + i;
        *(float4*)&C[(size_t)rr*N + col0 + tx*8]     = make_float4(acc[i][0], acc[i][1], acc[i][2], acc[i][3]);
        *(float4*)&C[(size_t)rr*N + col0 + tx*8 + 4] = make_float4(acc[i][4], acc[i][5], acc[i][6], acc[i][7]);
    }
    // mirror to upper tile
    if (btr != btc) {
        #pragma unroll
        for (int j = 0; j < 8; j++) {
            int cc = col0 + tx*8 + j;
            *(float4*)&C[(size_t)cc*N + row0 + ty*8]     = make_float4(acc[0][j], acc[1][j], acc[2][j], acc[3][j]);
            *(float4*)&C[(size_t)cc*N + row0 + ty*8 + 4] = make_float4(acc[4][j], acc[5][j], acc[6][j], acc[7][j]);
        }
    }
}

// betti[t] = s==0 ? tr(X) : ||X||_F^2   with X in buffer 5 (q even) or 4 (q odd)
__global__ void frob_kernel() {
    int t = blockIdx.x;
    int s = g_s[t], q = g_q[t];
    const float* X = g_buf[(q & 1) ? 4 : 5] + (size_t)t*NN;
    double acc = 0.0;
    if (s == 0) {
        for (int i = threadIdx.x; i < N; i += blockDim.x)
            acc += (double)X[(size_t)i*N + i];
    } else {
        for (int idx = threadIdx.x; idx < NN; idx += blockDim.x) {
            double v = X[idx];
            acc += v * v;
        }
    }
    __shared__ double red[256];
    red[threadIdx.x] = acc;
    __syncthreads();
    for (int off = 128; off > 0; off >>= 1) {
        if (threadIdx.x < off) red[threadIdx.x] += red[threadIdx.x+off];
        __syncthreads();
    }
    if (threadIdx.x == 0) g_betti[t] = (float)red[0];
}

__global__ void final_kernel(float* __restrict__ out) {
    __shared__ float b[NT];
    __shared__ float bi[RES], sm[RES], dv[RES];
    __shared__ float red;
    int tid = threadIdx.x;
    if (tid < NT) b[tid] = g_betti[tid];
    __syncthreads();
    if (tid < RES) {
        float pos = (float)(NT-1) * (float)tid / (float)(RES-1);
        int i0 = (int)floorf(pos);
        if (i0 > NT-2) i0 = NT-2;
        if (i0 < 0) i0 = 0;
        float fr = pos - (float)i0;
        bi[tid] = b[i0]*(1.0f - fr) + b[i0+1]*fr;
    }
    __syncthreads();
    if (tid == 0) {
        float m = bi[0];
        for (int i = 1; i < RES; i++) m = fmaxf(m, bi[i]);
        red = m;
    }
    __syncthreads();
    if (tid < RES) out[tid] = bi[tid] / (red + 1e-8f);

    for (int k = 1; k < NL; k++) {
        int ks = 2*k + 1;           // 3,5,7,9 (all < RES/4)
        int pad = ks / 2;
        __syncthreads();
        if (tid < RES) {
            float s = 0.0f;
            for (int u = -pad; u <= pad; u++) {
                int j = tid + u;
                j = max(0, min(RES-1, j));   // edge padding
                s += bi[j];
            }
            sm[tid] = s / (float)ks;
        }
        __syncthreads();
        if (tid < RES) {
            float d = (tid < RES-1) ? (sm[tid+1] - sm[tid]) : (sm[RES-1] - sm[RES-2]);
            dv[tid] = d;
        }
        __syncthreads();
        if (tid == 0) {
            float m = fabsf(dv[0]);
            for (int i = 1; i < RES; i++) m = fmaxf(m, fabsf(dv[i]));
            red = m;
        }
        __syncthreads();
        if (tid < RES) out[k*RES + tid] = dv[tid] / (red + 1e-8f);
    }
}

extern "C" void kernel_launch(void* const* d_in, const int* in_sizes, int n_in,
                              void* d_out, int out_size)
{
    const float* pts = (const float*)d_in[0];
    float* out = (float*)d_out;

    init_kernel<<<1, 64>>>();
    dist_kernel<<<NN/256, 256>>>(pts);
    rowsum_kernel<<<NT*N, 128>>>();
    sq_kernel<<<1, 64>>>();

    dim3 gE(NN/256, NT);
    buildM_kernel<<<gE, 256>>>();

    dim3 gG(21, 1, NT);
    // Taylor degree 15, Paterson-Stockmeyer q=4
    gemm_kernel<<<gG, 256>>>(0, 0, 1, 0, 0,0,0,0, -1);                 // M2 = M*M
    gemm_kernel<<<gG, 256>>>(1, 0, 2, 0, 0,0,0,0, -1);                 // M3 = M2*M
    gemm_kernel<<<gG, 256>>>(1, 1, 3, 0, 0,0,0,0, -1);                 // M4 = M2*M2
    elw_g3_kernel<<<gE, 256>>>();                                      // B4 = G3
    gemm_kernel<<<gG, 256>>>(3, 4, 5, 1, C8, C9, C10, C11, -1);        // B5 = M4*B4 + G2
    gemm_kernel<<<gG, 256>>>(3, 5, 4, 1, C4, C5, C6,  C7,  -1);        // B4 = M4*B5 + G1
    gemm_kernel<<<gG, 256>>>(3, 4, 5, 1, C0, C1, C2,  C3,  -1);        // B5 = M4*B4 + G0 = exp(M)

    // q = max(s-1,0) squarings; per-t gating inside kernel; ping-pong 5<->4
    for (int i = 0; i < S_ITERS; i++) {
        int src = (i & 1) ? 4 : 5;
        int dst = (i & 1) ? 5 : 4;
        gemm_kernel<<<gG, 256>>>(src, src, dst, 0, 0,0,0,0, i);
    }

    frob_kernel<<<NT, 256>>>();
    final_kernel<<<1, 128>>>(out);
}